// round 17
// baseline (speedup 1.0000x reference)
#include <cuda_runtime.h>
#include <math.h>

#define BB 64
#define PP 24564
#define CC 81
#define TT 24
#define THRESH_F 0.5f
#define FULLMASK 0xffffffffu

// fused kernel geometry: 740 blocks x 128 threads (2 conf + 2 match warps)
#define NBLK 740
#define CW_BUFS 2
#define CW_ROWS 32
#define CW_F4 ((CW_ROWS * CC) / 4)     // 648 float4 per tile
#define CW_TILEF (CW_ROWS * CC)        // 2592 floats
#define CONF_TILES ((BB * PP) / CW_ROWS)      // 49128
#define NCWARPS (NBLK * 2)             // 1480 conf warps
#define NMWARPS (NBLK * 2)             // 1480 match warps
#define MCH_PER_B 768                  // 32-prior chunks per batch
#define MCHUNKS (MCH_PER_B * BB)       // 49152
#define SMEM_CONF_F (2 * CW_BUFS * CW_TILEF)      // 10368 floats
#define FUSED_SMEM ((SMEM_CONF_F + 2 * 256) * 4)  // 43520 B -> 5 blocks/SM

#define HBINS 32768                    // 16-bit float-prefix bins per batch
#define CAND_CAP 6144                  // smem candidate buffer (bin-S members)

// ---------------------------------------------------------------------------
// Scratch (device globals — no allocation allowed)
// ---------------------------------------------------------------------------
__device__ unsigned long long g_bp[BB * TT];        // packed (iou_bits<<32)|~p
__device__ unsigned char g_match[(size_t)BB * PP];  // 0xFF = negative, else positive
__device__ float g_closs[(size_t)BB * PP];          // lse - c0 raw (ALL rows)
__device__ unsigned int g_plist[(size_t)BB * PP];   // packed (row<<8)|lbl
__device__ int g_hist[BB * HBINS];                  // per-batch closs histogram (u>>16)
__device__ int g_pcount;
__device__ double g_loc, g_poscls, g_negcls;
__device__ int g_numpos[BB];
__device__ int g_nsel;

__device__ __forceinline__ void cp_async16(unsigned int smem_dst, const void* gsrc) {
    asm volatile("cp.async.cg.shared.global [%0], [%1], 16;"
                 :: "r"(smem_dst), "l"(gsrc));
}

// ---------------------------------------------------------------------------
// Kernel 0: zero-init scratch (grid-stride; also zeros the 8 MB histogram)
// ---------------------------------------------------------------------------
__global__ void k_init() {
    const int gs = gridDim.x * blockDim.x;
    int i = blockIdx.x * blockDim.x + threadIdx.x;
    for (int j = i; j < BB * HBINS; j += gs) g_hist[j] = 0;
    if (i < BB * TT) g_bp[i] = 0ULL;
    if (i < BB) g_numpos[i] = 0;
    if (i == 0) { g_loc = 0.0; g_poscls = 0.0; g_negcls = 0.0; g_nsel = 0; g_pcount = 0; }
}

// ---------------------------------------------------------------------------
// Kernel 1 (FUSED, 2 conf : 2 match). Conf path additionally RED.ADDs each
// row's closs into the per-batch 16-bit-prefix histogram — this replaces
// k_select's full-data radix passes, hidden in conf's idle issue slots.
// ---------------------------------------------------------------------------
__global__ void __launch_bounds__(128) k_fused(const float* __restrict__ conf_pred,
                                               const float* __restrict__ loc_pred,
                                               const float* __restrict__ targets,
                                               const float* __restrict__ anchors) {
    extern __shared__ float smem[];
    const int lane = threadIdx.x & 31;
    const int w = threadIdx.x >> 5;

    if (w < 2) {
        // ================= CONF PATH =========================================
        const int gw = blockIdx.x * 2 + w;               // 0..1479
        float* wbase = smem + w * (CW_BUFS * CW_TILEF);
        unsigned int sb0 = (unsigned int)__cvta_generic_to_shared(wbase);

        int tile = gw;
        {
            const float4* src = (const float4*)(conf_pred + (size_t)tile * CW_TILEF);
            #pragma unroll
            for (int i = lane; i < CW_F4; i += 32)
                cp_async16(sb0 + i * 16, src + i);
            asm volatile("cp.async.commit_group;");
        }
        int buf = 0;
        for (; tile < CONF_TILES; tile += NCWARPS) {
            const int nt = tile + NCWARPS;
            if (nt < CONF_TILES) {
                const float4* src = (const float4*)(conf_pred + (size_t)nt * CW_TILEF);
                unsigned int dst = sb0 + (buf ^ 1) * (CW_TILEF * 4);
                #pragma unroll
                for (int i = lane; i < CW_F4; i += 32)
                    cp_async16(dst + i * 16, src + i);
            }
            asm volatile("cp.async.commit_group;");
            asm volatile("cp.async.wait_group 1;");
            __syncwarp();

            const float* rp = wbase + buf * CW_TILEF + lane * CC;
            float a0 = 0.f, a1 = 0.f, a2 = 0.f;
            #pragma unroll 9
            for (int e = 0; e < CC; e += 3) {
                a0 += __expf(rp[e]);
                a1 += __expf(rp[e + 1]);
                a2 += __expf(rp[e + 2]);
            }
            const float lse = __logf((a0 + a1) + a2);
            const float closs = lse - rp[0];                 // raw, ALL rows
            const unsigned int rw = (unsigned int)tile * CW_ROWS + lane;
            g_closs[rw] = closs;
            // histogram: closs >= 0 (lse >= c0) -> u>>16 < 32768 always
            atomicAdd(&g_hist[(rw / (unsigned int)PP) * HBINS
                              + (__float_as_uint(closs) >> 16)], 1);

            buf ^= 1;
            __syncwarp();
        }
    } else {
        // ================= MATCH PATH (1480 warps, ~33 chunks each) ==========
        const int gw2 = blockIdx.x * 2 + (w - 2);        // 0..1479
        float* tc = smem + SMEM_CONF_F + (w - 2) * 256;  // warp-private truth cache
        float* t_box = tc;            // [24][4] xyxy
        float* t_ta  = tc + 96;       // [24]
        float* t_cwh = tc + 120;      // [24][4]
        float* t_lbl = tc + 216;      // [24]

        const int c0 = (int)(((long long)gw2 * MCHUNKS) / NMWARPS);
        const int c1 = (int)(((long long)(gw2 + 1) * MCHUNKS) / NMWARPS);

        unsigned int cur[TT];         // warp-uniform running max (iou bits)
        int bcur = -1;

        for (int c = c0; c < c1; c++) {
            const int b = c / MCH_PER_B;
            const int p = (c - b * MCH_PER_B) * 32 + lane;
            if (b != bcur) {
                __syncwarp();
                if (lane < TT) {
                    const float* tr = targets + ((size_t)b * TT + lane) * 5;
                    float x0 = tr[0], y0 = tr[1], x1 = tr[2], y1 = tr[3];
                    t_box[lane * 4 + 0] = x0; t_box[lane * 4 + 1] = y0;
                    t_box[lane * 4 + 2] = x1; t_box[lane * 4 + 3] = y1;
                    t_ta[lane] = (x1 - x0) * (y1 - y0);
                    t_cwh[lane * 4 + 0] = (x0 + x1) * 0.5f;
                    t_cwh[lane * 4 + 1] = (y0 + y1) * 0.5f;
                    t_cwh[lane * 4 + 2] = x1 - x0;
                    t_cwh[lane * 4 + 3] = y1 - y0;
                    t_lbl[lane] = tr[4];
                }
                __syncwarp();
                #pragma unroll
                for (int t = 0; t < TT; t++) cur[t] = 0u;
                bcur = b;
            }

            const bool valid = (p < PP);
            float4 a = make_float4(0.f, 0.f, 1.f, 1.f);
            if (valid) a = ((const float4*)anchors)[p];
            const float ax0 = a.x - a.z * 0.5f, ay0 = a.y - a.w * 0.5f;
            const float ax1 = a.x + a.z * 0.5f, ay1 = a.y + a.w * 0.5f;
            const float aarea = (ax1 - ax0) * (ay1 - ay0);

            float best = -1.0f; int bt = 0;
            #pragma unroll
            for (int t = 0; t < TT; t++) {
                float lx = fmaxf(t_box[t * 4 + 0], ax0), ly = fmaxf(t_box[t * 4 + 1], ay0);
                float rx = fminf(t_box[t * 4 + 2], ax1), ry = fminf(t_box[t * 4 + 3], ay1);
                float ww = fmaxf(rx - lx, 0.f), hh = fmaxf(ry - ly, 0.f);
                float inter = ww * hh;
                float iou = __fdividef(inter, t_ta[t] + aarea - inter);
                if (iou > best) { best = iou; bt = t; }   // strict >: first index
                unsigned int ib = valid ? __float_as_uint(iou) : 0u;
                if (__any_sync(FULLMASK, ib > cur[t])) {
                    unsigned long long pk = valid
                        ? (((unsigned long long)ib << 32)
                           | (unsigned long long)(unsigned int)(~p))
                        : 0ULL;
                    #pragma unroll
                    for (int o = 16; o; o >>= 1) {
                        unsigned long long q = __shfl_xor_sync(FULLMASK, pk, o);
                        if (q > pk) pk = q;
                    }
                    cur[t] = (unsigned int)(pk >> 32);
                    if (lane == 0) atomicMax(&g_bp[b * TT + t], pk);
                }
            }

            const bool pos = valid && (best > THRESH_F);
            const unsigned int pm = __ballot_sync(FULLMASK, pos);
            const unsigned int row = (unsigned int)(b * PP + p);
            float lt = 0.f; int lbl = 0;
            if (pos) {
                lbl = (int)t_lbl[bt];
                float4 lp = ((const float4*)loc_pred)[row];
                float e0 = (t_cwh[bt * 4 + 0] - a.x) / a.z;
                float e1 = (t_cwh[bt * 4 + 1] - a.y) / a.w;
                float e2 = __logf(t_cwh[bt * 4 + 2]) - __logf(a.z);
                float e3 = __logf(t_cwh[bt * 4 + 3]) - __logf(a.w);
                float d, ad;
                d = lp.x - e0; ad = fabsf(d); lt += (ad < 1.f) ? 0.5f * d * d : ad - 0.5f;
                d = lp.y - e1; ad = fabsf(d); lt += (ad < 1.f) ? 0.5f * d * d : ad - 0.5f;
                d = lp.z - e2; ad = fabsf(d); lt += (ad < 1.f) ? 0.5f * d * d : ad - 0.5f;
                d = lp.w - e3; ad = fabsf(d); lt += (ad < 1.f) ? 0.5f * d * d : ad - 0.5f;
            }
            if (pm) {   // warp-aggregated positive bookkeeping
                const int n = __popc(pm);
                const int leader = __ffs(pm) - 1;
                unsigned int base = 0;
                if (lane == leader) base = (unsigned int)atomicAdd(&g_pcount, n);
                base = __shfl_sync(FULLMASK, base, leader);
                if (pos) {
                    int off = __popc(pm & ((1u << lane) - 1u));
                    g_plist[base + off] = (row << 8) | (unsigned int)lbl;
                }
                double dlt = (double)lt;
                #pragma unroll
                for (int o = 16; o; o >>= 1) dlt += __shfl_xor_sync(FULLMASK, dlt, o);
                if (lane == leader) {
                    atomicAdd(&g_loc, dlt);
                    atomicAdd(&g_numpos[b], n);
                }
            }
            if (valid) g_match[row] = pos ? (unsigned char)bt : (unsigned char)0xFF;
        }
    }
}

// ---------------------------------------------------------------------------
// Kernel 2: scatter fixup — row p = best_prior[b][t] becomes positive with
// truth t (last t wins among duplicates) iff its best overlap <= 0.5.
// ---------------------------------------------------------------------------
__global__ void k_fix(const float* __restrict__ loc_pred,
                      const float* __restrict__ targets,
                      const float* __restrict__ anchors) {
    const int b = blockIdx.x;
    const int t = threadIdx.x;
    if (t >= TT) return;
    unsigned long long pk = g_bp[b * TT + t];
    const int p = (int)(~(unsigned int)(pk & 0xFFFFFFFFull));
    unsigned int peers = __match_any_sync(0x00FFFFFFu, p);
    if (t != 31 - __clz(peers)) return;          // last t wins
    const unsigned int row = (unsigned int)(b * PP + p);
    if (g_match[row] != 0xFF) return;            // bt-match already positive
    g_match[row] = (unsigned char)t;             // mark positive

    const float* tr = targets + ((size_t)b * TT + t) * 5;
    float x0 = tr[0], y0 = tr[1], x1 = tr[2], y1 = tr[3];
    int lbl = (int)tr[4];
    int idx = atomicAdd(&g_pcount, 1);
    g_plist[idx] = (row << 8) | (unsigned int)lbl;

    float4 a = ((const float4*)anchors)[p];
    float4 lp = ((const float4*)loc_pred)[row];
    float e0 = ((x0 + x1) * 0.5f - a.x) / a.z;
    float e1 = ((y0 + y1) * 0.5f - a.y) / a.w;
    float e2 = __logf(x1 - x0) - __logf(a.z);
    float e3 = __logf(y1 - y0) - __logf(a.w);
    float d, ad, lt = 0.f;
    d = lp.x - e0; ad = fabsf(d); lt += (ad < 1.f) ? 0.5f * d * d : ad - 0.5f;
    d = lp.y - e1; ad = fabsf(d); lt += (ad < 1.f) ? 0.5f * d * d : ad - 0.5f;
    d = lp.z - e2; ad = fabsf(d); lt += (ad < 1.f) ? 0.5f * d * d : ad - 0.5f;
    d = lp.w - e3; ad = fabsf(d); lt += (ad < 1.f) ? 0.5f * d * d : ad - 0.5f;
    atomicAdd(&g_loc, (double)lt);
    atomicAdd(&g_numpos[b], 1);
}

// ---------------------------------------------------------------------------
// Kernel 3: k_select v3 — histogram is PRE-BUILT by k_fused. Steps:
//  1. plist scan: decrement own-batch bins (positives out) + poscls gather
//  2. 3-level parallel suffix-select over 32768 bins -> bin S, rank r
//  3. ONE data pass: sum/count above bin S; collect bin-S candidates to smem
//  4. 2x256-bin refinement over candidates (16 low bits) -> exact theta
// ---------------------------------------------------------------------------
__global__ void __launch_bounds__(1024) k_select(const float* __restrict__ conf_pred) {
    __shared__ float cand[CAND_CAP];
    __shared__ int hist2[256];
    __shared__ int csum[32];
    __shared__ int wt[8];
    __shared__ int s_chunk, s_r2, s_sub, s_bin, s_rb;
    __shared__ int s_a, s_ra, s_b2;
    __shared__ int s_m, s_cnt;
    __shared__ double s_hi;

    const int b = blockIdx.x;
    const int tid = threadIdx.x;
    const int lane = tid & 31;
    const int w = tid >> 5;
    int* hb = g_hist + b * HBINS;

    // ---- 1. plist scan: own-batch decrements + poscls slice (i&63)==b ----
    {
        const int n = g_pcount;
        double acc = 0.0;
        for (int i = tid; i < n; i += 1024) {
            unsigned int e = g_plist[i];
            unsigned int row = e >> 8;
            if (row / (unsigned int)PP == (unsigned int)b) {
                unsigned int u = __float_as_uint(g_closs[row]);
                atomicSub(&hb[u >> 16], 1);
            }
            if ((i & 63) == b) {
                int lbl = (int)(e & 255u);
                const float* cp = conf_pred + (size_t)row * CC;
                acc += (double)(g_closs[row] + __ldg(cp) - __ldg(cp + lbl));
            }
        }
        #pragma unroll
        for (int o = 16; o; o >>= 1) acc += __shfl_xor_sync(FULLMASK, acc, o);
        if (lane == 0 && acc != 0.0) atomicAdd(&g_poscls, acc);
    }

    const int np = g_numpos[b];
    long long Kl = 3LL * np;
    if (Kl > PP - 1) Kl = PP - 1;
    const int K = (int)Kl;
    if (K <= 0) {
        if (tid == 0) atomicAdd(&g_nsel, np);
        return;
    }

    if (tid == 0) { s_m = 0; s_cnt = 0; s_hi = 0.0; }
    __syncthreads();   // decrements visible before hist reads

    // ---- 2. three-level suffix select over 32768 bins ----
    {   // level 1: warp w sums its 1024-bin chunk (coalesced)
        int wsum = 0;
        const int base = w * 1024;
        for (int it = 0; it < 32; it++) wsum += hb[base + it * 32 + lane];
        #pragma unroll
        for (int o = 16; o; o >>= 1) wsum += __shfl_xor_sync(FULLMASK, wsum, o);
        if (lane == 0) csum[w] = wsum;
    }
    __syncthreads();
    if (w == 0) {       // level 2: suffix over 32 chunk sums
        int c = csum[lane];
        int sfx = c;
        #pragma unroll
        for (int o = 1; o < 32; o <<= 1) {
            int y = __shfl_down_sync(FULLMASK, sfx, o);
            if (lane + o < 32) sfx += y;
        }
        if (sfx >= K && sfx - c < K) { s_chunk = lane; s_r2 = K - (sfx - c); }
    }
    __syncthreads();
    if (w == 0) {       // level 3: suffix over 32 sub-sums of the chunk
        const int base = s_chunk * 1024 + lane * 32;
        int ls = 0;
        for (int j = 0; j < 32; j++) ls += hb[base + j];
        int sfx = ls;
        #pragma unroll
        for (int o = 1; o < 32; o <<= 1) {
            int y = __shfl_down_sync(FULLMASK, sfx, o);
            if (lane + o < 32) sfx += y;
        }
        if (sfx >= s_r2 && sfx - ls < s_r2) { s_sub = lane; s_rb = s_r2 - (sfx - ls); }
    }
    __syncthreads();
    if (tid == 0) {     // level 4: serial over 32 bins, descending
        const int base = s_chunk * 1024 + s_sub * 32;
        int r3 = s_rb;
        for (int j = 31; j >= 0; j--) {
            int h = hb[base + j];
            if (h >= r3) { s_bin = base + j; s_rb = r3; break; }
            r3 -= h;
        }
    }
    __syncthreads();
    const unsigned int S = (unsigned int)s_bin;
    const int r = s_rb;

    // ---- 3. single data pass: above-bin sum + bin-S candidate collection ----
    const float* cl = g_closs + (size_t)b * PP;
    const unsigned char* gm = g_match + (size_t)b * PP;
    {
        double hi = 0.0; int chi = 0;
        #pragma unroll
        for (int i = 0; i < 24; i++) {
            int idx = tid + i * 1024;
            if (idx < PP && gm[idx] == 0xFF) {
                float f = cl[idx];
                unsigned int bin = __float_as_uint(f) >> 16;
                if (bin > S) { hi += (double)f; chi++; }
                else if (bin == S) {
                    int pos = atomicAdd(&s_m, 1);
                    if (pos < CAND_CAP) cand[pos] = f;
                }
            }
        }
        #pragma unroll
        for (int o = 16; o; o >>= 1) {
            hi += __shfl_xor_sync(FULLMASK, hi, o);
            chi += __shfl_xor_sync(FULLMASK, chi, o);
        }
        if (lane == 0) { atomicAdd(&s_hi, hi); atomicAdd(&s_cnt, chi); }
    }
    __syncthreads();
    const int m = (s_m < CAND_CAP) ? s_m : CAND_CAP;

    // ---- 4. refinement: 2x256-bin radix over candidates' low 16 bits ----
    if (tid < 256) hist2[tid] = 0;
    __syncthreads();
    for (int j = tid; j < m; j += 1024)
        atomicAdd(&hist2[(__float_as_uint(cand[j]) >> 8) & 255u], 1);
    __syncthreads();
    int h = 0, x = 0;
    if (tid < 256) {
        h = hist2[tid]; x = h;
        #pragma unroll
        for (int o = 1; o < 32; o <<= 1) {
            int y = __shfl_down_sync(FULLMASK, x, o);
            if (lane + o < 32) x += y;
        }
        if (lane == 0) wt[tid >> 5] = x;
        hist2[tid] = 0;
    }
    __syncthreads();
    if (tid < 256) {
        int add = 0; const int wi = tid >> 5;
        #pragma unroll
        for (int wj = 0; wj < 8; wj++) if (wj > wi) add += wt[wj];
        int sfx = x + add;
        if (sfx >= r && sfx - h < r) { s_a = tid; s_ra = r - (sfx - h); }
    }
    __syncthreads();
    const unsigned int A = (unsigned int)s_a;
    const int r2 = s_ra;
    for (int j = tid; j < m; j += 1024) {
        unsigned int u = __float_as_uint(cand[j]);
        if (((u >> 8) & 255u) == A) atomicAdd(&hist2[u & 255u], 1);
    }
    __syncthreads();
    h = 0; x = 0;
    if (tid < 256) {
        h = hist2[tid]; x = h;
        #pragma unroll
        for (int o = 1; o < 32; o <<= 1) {
            int y = __shfl_down_sync(FULLMASK, x, o);
            if (lane + o < 32) x += y;
        }
        if (lane == 0) wt[tid >> 5] = x;
    }
    __syncthreads();
    if (tid < 256) {
        int add = 0; const int wi = tid >> 5;
        #pragma unroll
        for (int wj = 0; wj < 8; wj++) if (wj > wi) add += wt[wj];
        int sfx = x + add;
        if (sfx >= r2 && sfx - h < r2) s_b2 = tid;
    }
    __syncthreads();
    const float theta = __uint_as_float((S << 16) | (A << 8) | (unsigned int)s_b2);

    // ---- 5. candidates above theta + combine ----
    {
        double cs = 0.0; int cc = 0;
        for (int j = tid; j < m; j += 1024) {
            float f = cand[j];
            if (f > theta) { cs += (double)f; cc++; }
        }
        #pragma unroll
        for (int o = 16; o; o >>= 1) {
            cs += __shfl_xor_sync(FULLMASK, cs, o);
            cc += __shfl_xor_sync(FULLMASK, cc, o);
        }
        if (lane == 0) { atomicAdd(&s_hi, cs); atomicAdd(&s_cnt, cc); }
    }
    __syncthreads();
    if (tid == 0) {
        double negsum = s_hi + (double)(K - s_cnt) * (double)theta;
        atomicAdd(&g_negcls, negsum);
        atomicAdd(&g_nsel, np + K);
    }
}

// ---------------------------------------------------------------------------
// Kernel 4: combine (non-selected rows each contribute exactly log C).
// ---------------------------------------------------------------------------
__global__ void k_final(float* out) {
    const int t = threadIdx.x;           // 64 threads
    int np = (t < BB) ? g_numpos[t] : 0;
    #pragma unroll
    for (int o = 16; o; o >>= 1) np += __shfl_xor_sync(FULLMASK, np, o);
    __shared__ int s_np[2];
    if ((t & 31) == 0) s_np[t >> 5] = np;
    __syncthreads();
    if (t == 0) {
        double N = (double)(s_np[0] + s_np[1]);
        double cls = g_poscls + g_negcls +
                     (double)((long long)BB * PP - (long long)g_nsel) * log((double)CC);
        out[0] = (float)(g_loc / N);
        out[1] = (float)(cls / N);
    }
}

// ---------------------------------------------------------------------------
// Launch
// ---------------------------------------------------------------------------
extern "C" void kernel_launch(void* const* d_in, const int* in_sizes, int n_in,
                              void* d_out, int out_size) {
    const float *loc = nullptr, *conf = nullptr, *tgt = nullptr, *anc = nullptr;
    for (int i = 0; i < n_in; i++) {
        long long s = in_sizes[i];
        if (s == (long long)BB * PP * 4)       loc  = (const float*)d_in[i];
        else if (s == (long long)BB * PP * CC) conf = (const float*)d_in[i];
        else if (s == (long long)BB * TT * 5)  tgt  = (const float*)d_in[i];
        else if (s == (long long)PP * 4)       anc  = (const float*)d_in[i];
    }
    float* out = (float*)d_out;

    k_init<<<2048, 256>>>();                                  // 1 (zeros 8 MB hist)
    k_fused<<<NBLK, 128, FUSED_SMEM>>>(conf, loc, tgt, anc);  // 2 (2:2 + hist RED)
    k_fix<<<BB, 32>>>(loc, tgt, anc);                         // 3
    k_select<<<BB, 1024>>>(conf);                             // 4 <- profiled
    k_final<<<1, 64>>>(out);                                  // 5
}